// round 11
// baseline (speedup 1.0000x reference)
#include <cuda_runtime.h>
#include <cuda_bf16.h>

// Problem constants
#define BB 4
#define HH 8
#define NN 4096
#define DD 64
#define RR 256
#define BH (BB*HH)
#define SCALE 0.35355339059327373f   // 64^(-1/4)
#define EPS 0.001f

#define SPLIT 8                   // CTAs per (b,h)
#define ROWS_CTA (NN/SPLIT)       // 512
#define TILES (ROWS_CTA/128)      // 4

// Scratch: ctxT [BH][64][256] (d-major), ksum [BH][256]
__device__ float g_ctxT[BH * 64 * 256];
__device__ float g_ksum[BH * 256];

// ---------------------------------------------------------------------------
// helpers
// ---------------------------------------------------------------------------
__device__ __forceinline__ unsigned f2tf(float f) {
    unsigned u;
    asm("cvt.rna.tf32.f32 %0, %1;" : "=r"(u) : "f"(f));
    return u;
}

// D += A@B : m16n8k8 tf32, A row-major (4 regs), B col-major (2 regs), D f32 (4 regs)
__device__ __forceinline__ void mma8(float* d, const unsigned* a, const unsigned* b) {
    asm("mma.sync.aligned.m16n8k8.row.col.f32.tf32.tf32.f32 "
        "{%0,%1,%2,%3},{%4,%5,%6,%7},{%8,%9},{%0,%1,%2,%3};"
        : "+f"(d[0]), "+f"(d[1]), "+f"(d[2]), "+f"(d[3])
        : "r"(a[0]), "r"(a[1]), "r"(a[2]), "r"(a[3]), "r"(b[0]), "r"(b[1]));
}

// ---------------------------------------------------------------------------
// zero scratch (graph replays)
// ---------------------------------------------------------------------------
__global__ void zero_kernel() {
    int i = blockIdx.x * blockDim.x + threadIdx.x;
    if (i < BH * 64 * 256) g_ctxT[i] = 0.0f;
    if (i < BH * 256)      g_ksum[i] = 0.0f;
}

// ---------------------------------------------------------------------------
// Pass A: per 128-row tile:
//   GEMM1: phi_k chunk = relu((K*m) @ projs^T) + eps   (4 chunks of 64 feats)
//          A-fragments (K) register-cached across chunks.
//          ksum accumulated exactly in epilogue (shfl + smem atomics).
//   GEMM2: ctxT[64,chunk64] += vt[64,128] @ phit ;  warps 4m x 2n
// smem words: projs 17408 | km 8704 | vt 64*132=8448 | phit x2 = 16896 | ksum 256
// total 51712 words = 206848 B
// ---------------------------------------------------------------------------
#define A_SMEM_WORDS (17408 + 8704 + 8448 + 2*8448 + 256)
#define A_SMEM_BYTES (A_SMEM_WORDS * 4)

__global__ void __launch_bounds__(256) passA_tc(
    const float* __restrict__ Kg, const float* __restrict__ Vg,
    const float* __restrict__ maskg, const float* __restrict__ projg)
{
    extern __shared__ unsigned sm[];
    const int S_PROJ  = 0;
    const int S_KM    = 17408;
    const int S_VT    = 26112;
    const int S_PHIT0 = 34560;
    const int S_PHIT1 = 43008;
    const int S_KSUM  = 51456;
    float* ksum_s = (float*)(sm + S_KSUM);

    const int t = threadIdx.x;
    const int warp = t >> 5, lane = t & 31;
    const int g = lane >> 2, tq = lane & 3;

    const int bh   = blockIdx.x / SPLIT;
    const int sl   = blockIdx.x % SPLIT;
    const int b    = bh / HH;
    const int row0 = sl * ROWS_CTA;

    // projs = proj * SCALE (tf32), [feat][d] stride 68  (16384 elems)
    #pragma unroll 4
    for (int i = 0; i < 64; ++i) {
        int e = i * 256 + t;
        int f = e >> 6, d = e & 63;
        sm[S_PROJ + f * 68 + d] = f2tf(projg[e] * SCALE);
    }
    ksum_s[t] = 0.0f;

    // persistent ctx accumulators: [chunk fc][ni(4)][4]  (warp tile m16 x n32)
    float ctxA[4][4][4];
    #pragma unroll
    for (int a = 0; a < 4; ++a)
        #pragma unroll
        for (int n = 0; n < 4; ++n)
            #pragma unroll
            for (int j = 0; j < 4; ++j) ctxA[a][n][j] = 0.0f;

    const int wm = warp >> 1, wn = warp & 1;

    for (int tile = 0; tile < TILES; ++tile) {
        __syncthreads();   // guard km/vt overwrite vs previous tile's reads

        const float* Kp = Kg + ((size_t)bh * NN + row0 + tile * 128) * 64;
        const float* Vp = Vg + ((size_t)bh * NN + row0 + tile * 128) * 64;
        const float* mp = maskg + (size_t)b * NN + row0 + tile * 128;

        // km[row][d] = K*m (stride 68); vt[d][row] = V*m transposed (stride 132)
        #pragma unroll 4
        for (int i = 0; i < 32; ++i) {
            int e = i * 256 + t;
            int r = e >> 6, d = e & 63;
            float m = mp[r];
            sm[S_KM + r * 68 + d]  = f2tf(Kp[e] * m);
            sm[S_VT + d * 132 + r] = f2tf(Vp[e] * m);
        }
        __syncthreads();

        // cache GEMM1 A-fragments (K rows of this warp) across all 4 fc chunks
        unsigned afr_c[8][2][4];
        #pragma unroll
        for (int ks = 0; ks < 8; ++ks) {
            int kc = ks * 8 + tq;
            #pragma unroll
            for (int mi = 0; mi < 2; ++mi) {
                int r = 32 * wm + 16 * mi + g;
                const unsigned* p = sm + S_KM + r * 68 + kc;
                afr_c[ks][mi][0] = p[0]; afr_c[ks][mi][1] = p[8 * 68];
                afr_c[ks][mi][2] = p[4]; afr_c[ks][mi][3] = p[8 * 68 + 4];
            }
        }

        #pragma unroll
        for (int fc = 0; fc < 4; ++fc) {
            const int S_PHIT = (fc & 1) ? S_PHIT1 : S_PHIT0;

            // ---- GEMM1: phi chunk [128 x 64], warps 4m x 2n ----
            float acc[2][4][4];
            #pragma unroll
            for (int mi = 0; mi < 2; ++mi)
                #pragma unroll
                for (int ni = 0; ni < 4; ++ni)
                    #pragma unroll
                    for (int j = 0; j < 4; ++j) acc[mi][ni][j] = 0.0f;

            #pragma unroll
            for (int ks = 0; ks < 8; ++ks) {
                int kc = ks * 8 + tq;
                #pragma unroll
                for (int ni = 0; ni < 4; ++ni) {
                    int nf = fc * 64 + 32 * wn + 8 * ni + g;
                    const unsigned* p = sm + S_PROJ + nf * 68 + kc;
                    unsigned bfr[2] = { p[0], p[4] };
                    mma8(acc[0][ni], afr_c[ks][0], bfr);
                    mma8(acc[1][ni], afr_c[ks][1], bfr);
                }
            }

            // epilogue: relu + eps; ksum (exact fp32, shfl over rows); transposed store
            #pragma unroll
            for (int ni = 0; ni < 4; ++ni) {
                float p00, p01, p02, p03, p10, p11, p12, p13;
                p00 = fmaxf(acc[0][ni][0], 0.f) + EPS;
                p01 = fmaxf(acc[0][ni][1], 0.f) + EPS;
                p02 = fmaxf(acc[0][ni][2], 0.f) + EPS;
                p03 = fmaxf(acc[0][ni][3], 0.f) + EPS;
                p10 = fmaxf(acc[1][ni][0], 0.f) + EPS;
                p11 = fmaxf(acc[1][ni][1], 0.f) + EPS;
                p12 = fmaxf(acc[1][ni][2], 0.f) + EPS;
                p13 = fmaxf(acc[1][ni][3], 0.f) + EPS;

                int r = 32 * wm + g;
                int c = 32 * wn + 8 * ni + 2 * tq;
                sm[S_PHIT + c       * 132 + r     ] = f2tf(p00);
                sm[S_PHIT + (c + 1) * 132 + r     ] = f2tf(p01);
                sm[S_PHIT + c       * 132 + r +  8] = f2tf(p02);
                sm[S_PHIT + (c + 1) * 132 + r +  8] = f2tf(p03);
                sm[S_PHIT + c       * 132 + r + 16] = f2tf(p10);
                sm[S_PHIT + (c + 1) * 132 + r + 16] = f2tf(p11);
                sm[S_PHIT + c       * 132 + r + 24] = f2tf(p12);
                sm[S_PHIT + (c + 1) * 132 + r + 24] = f2tf(p13);

                // column sums over this warp's 32 rows
                float s0 = (p00 + p02) + (p10 + p12);   // col c
                float s1 = (p01 + p03) + (p11 + p13);   // col c+1
                #pragma unroll
                for (int off = 4; off < 32; off <<= 1) {
                    s0 += __shfl_xor_sync(0xFFFFFFFF, s0, off);
                    s1 += __shfl_xor_sync(0xFFFFFFFF, s1, off);
                }
                if (g == 0) {
                    atomicAdd(&ksum_s[fc * 64 + c],     s0);
                    atomicAdd(&ksum_s[fc * 64 + c + 1], s1);
                }
            }
            __syncthreads();

            // ---- GEMM2: ctx[64 x 64chunk] += vt[64,128] @ phit ; warps 4m x 2n ----
            #pragma unroll
            for (int ks = 0; ks < 16; ++ks) {
                int kc = ks * 8 + tq;
                const unsigned* pa = sm + S_VT + (16 * wm + g) * 132 + kc;
                unsigned afr[4] = { pa[0], pa[8 * 132], pa[4], pa[8 * 132 + 4] };
                #pragma unroll
                for (int ni = 0; ni < 4; ++ni) {
                    const unsigned* pb = sm + S_PHIT + (32 * wn + 8 * ni + g) * 132 + kc;
                    unsigned bfr[2] = { pb[0], pb[4] };
                    mma8(ctxA[fc][ni], afr, bfr);
                }
            }
            // no trailing sync: next GEMM1 writes the other phit buffer
        }
    }
    __syncthreads();

    // write partials
    atomicAdd(&g_ksum[bh * 256 + t], ksum_s[t]);
    #pragma unroll
    for (int fc = 0; fc < 4; ++fc)
        #pragma unroll
        for (int ni = 0; ni < 4; ++ni) {
            int d0 = 16 * wm + g;
            int feat = fc * 64 + 32 * wn + 8 * ni + 2 * tq;
            float* p0 = g_ctxT + ((size_t)bh * 64 + d0    ) * 256 + feat;
            float* p1 = g_ctxT + ((size_t)bh * 64 + d0 + 8) * 256 + feat;
            atomicAdd(p0,     ctxA[fc][ni][0]);
            atomicAdd(p0 + 1, ctxA[fc][ni][1]);
            atomicAdd(p1,     ctxA[fc][ni][2]);
            atomicAdd(p1 + 1, ctxA[fc][ni][3]);
        }
}

// ---------------------------------------------------------------------------
// Pass B: per 128-row tile:
//   GEMM1': phi_q chunk = relu(Q @ projs^T) + eps  (Q-frags register-cached)
//   GEMM3 : outraw[128,80] += phi_q @ ctx^T  (ctx row 64 = ksum -> denominator)
// smem words: projs 17408 | qs 8704 | phiq 8704 | ctx 80*260=20800 | den 128
// ---------------------------------------------------------------------------
#define B_SMEM_WORDS (17408 + 8704 + 8704 + 20800 + 128)
#define B_SMEM_BYTES (B_SMEM_WORDS * 4)

__global__ void __launch_bounds__(256) passB_tc(
    const float* __restrict__ Qg, const float* __restrict__ projg,
    float* __restrict__ outg)
{
    extern __shared__ unsigned sm[];
    const int S_PROJ = 0;
    const int S_Q    = 17408;
    const int S_PHIQ = 26112;
    const int S_CTX  = 34816;
    const int S_DEN  = 55616;
    float* denS = (float*)(sm + S_DEN);

    const int t = threadIdx.x;
    const int warp = t >> 5, lane = t & 31;
    const int g = lane >> 2, tq = lane & 3;

    const int bh   = blockIdx.x / SPLIT;
    const int sl   = blockIdx.x % SPLIT;
    const int row0 = sl * ROWS_CTA;

    // projs (16384 elems)
    #pragma unroll 4
    for (int i = 0; i < 64; ++i) {
        int e = i * 256 + t;
        int f = e >> 6, d = e & 63;
        sm[S_PROJ + f * 68 + d] = f2tf(projg[e] * SCALE);
    }
    // ctx [d][feat] stride 260: rows 0-63 = ctxT, row 64 = ksum, rows 65-79 = 0
    #pragma unroll 4
    for (int i = 0; i < 64; ++i) {
        int e = i * 256 + t;
        int d = e >> 8, f = e & 255;
        sm[S_CTX + d * 260 + f] = f2tf(g_ctxT[(size_t)bh * 16384 + e]);
    }
    sm[S_CTX + 64 * 260 + t] = f2tf(g_ksum[bh * 256 + t]);
    #pragma unroll
    for (int d = 65; d < 80; ++d)
        if (t < 256) sm[S_CTX + d * 260 + t] = 0u;

    const int wm = warp >> 1, wn = warp & 1;

    for (int tile = 0; tile < TILES; ++tile) {
        __syncthreads();

        const float* Qp = Qg + ((size_t)bh * NN + row0 + tile * 128) * 64;
        #pragma unroll 4
        for (int i = 0; i < 32; ++i) {
            int e = i * 256 + t;
            int r = e >> 6, d = e & 63;
            sm[S_Q + r * 68 + d] = f2tf(Qp[e]);
        }
        __syncthreads();

        // cache GEMM1' A-fragments (Q rows) across fc chunks
        unsigned afr_c[8][2][4];
        #pragma unroll
        for (int ks = 0; ks < 8; ++ks) {
            int kc = ks * 8 + tq;
            #pragma unroll
            for (int mi = 0; mi < 2; ++mi) {
                int r = 32 * wm + 16 * mi + g;
                const unsigned* p = sm + S_Q + r * 68 + kc;
                afr_c[ks][mi][0] = p[0]; afr_c[ks][mi][1] = p[8 * 68];
                afr_c[ks][mi][2] = p[4]; afr_c[ks][mi][3] = p[8 * 68 + 4];
            }
        }

        // persistent out accumulators: warp tile 32(m) x 40(n)
        float accO[2][5][4];
        #pragma unroll
        for (int mi = 0; mi < 2; ++mi)
            #pragma unroll
            for (int ni = 0; ni < 5; ++ni)
                #pragma unroll
                for (int j = 0; j < 4; ++j) accO[mi][ni][j] = 0.0f;

        #pragma unroll
        for (int fc = 0; fc < 4; ++fc) {
            // ---- GEMM1': phi_q chunk [128 x 64] ----
            float acc[2][4][4];
            #pragma unroll
            for (int mi = 0; mi < 2; ++mi)
                #pragma unroll
                for (int ni = 0; ni < 4; ++ni)
                    #pragma unroll
                    for (int j = 0; j < 4; ++j) acc[mi][ni][j] = 0.0f;

            #pragma unroll
            for (int ks = 0; ks < 8; ++ks) {
                int kc = ks * 8 + tq;
                #pragma unroll
                for (int ni = 0; ni < 4; ++ni) {
                    int nf = fc * 64 + 32 * wn + 8 * ni + g;
                    const unsigned* p = sm + S_PROJ + nf * 68 + kc;
                    unsigned bfr[2] = { p[0], p[4] };
                    mma8(acc[0][ni], afr_c[ks][0], bfr);
                    mma8(acc[1][ni], afr_c[ks][1], bfr);
                }
            }
            // store phiq[row][c] (chunk-local, stride 68)
            #pragma unroll
            for (int mi = 0; mi < 2; ++mi)
                #pragma unroll
                for (int ni = 0; ni < 4; ++ni) {
                    int r = 32 * wm + 16 * mi + g;
                    int c = 32 * wn + 8 * ni + 2 * tq;
                    sm[S_PHIQ + r       * 68 + c    ] = f2tf(fmaxf(acc[mi][ni][0], 0.f) + EPS);
                    sm[S_PHIQ + r       * 68 + c + 1] = f2tf(fmaxf(acc[mi][ni][1], 0.f) + EPS);
                    sm[S_PHIQ + (r + 8) * 68 + c    ] = f2tf(fmaxf(acc[mi][ni][2], 0.f) + EPS);
                    sm[S_PHIQ + (r + 8) * 68 + c + 1] = f2tf(fmaxf(acc[mi][ni][3], 0.f) + EPS);
                }
            __syncthreads();

            // ---- GEMM3 partial: outraw += phiq @ ctx^T (k = this chunk's 64 feats) ----
            #pragma unroll
            for (int ks = 0; ks < 8; ++ks) {
                int kc = ks * 8 + tq;
                unsigned afr[2][4];
                #pragma unroll
                for (int mi = 0; mi < 2; ++mi) {
                    int r = 32 * wm + 16 * mi + g;
                    const unsigned* p = sm + S_PHIQ + r * 68 + kc;
                    afr[mi][0] = p[0]; afr[mi][1] = p[8 * 68];
                    afr[mi][2] = p[4]; afr[mi][3] = p[8 * 68 + 4];
                }
                #pragma unroll
                for (int ni = 0; ni < 5; ++ni) {
                    int n = 40 * wn + 8 * ni + g;
                    const unsigned* p = sm + S_CTX + n * 260 + fc * 64 + kc;
                    unsigned bfr[2] = { p[0], p[4] };
                    mma8(accO[0][ni], afr[0], bfr);
                    mma8(accO[1][ni], afr[1], bfr);
                }
            }
            __syncthreads();   // phiq reuse guard
        }

        // denominator: col 64 lives in warps wn==1, frag ni=3, lanes tq==0, elem 0/2
        if (wn == 1 && tq == 0) {
            #pragma unroll
            for (int mi = 0; mi < 2; ++mi) {
                int r = 32 * wm + 16 * mi + g;
                denS[r]     = accO[mi][3][0];
                denS[r + 8] = accO[mi][3][2];
            }
        }
        __syncthreads();

        // scaled store
        float* Op = outg + ((size_t)bh * NN + row0 + tile * 128) * 64;
        #pragma unroll
        for (int mi = 0; mi < 2; ++mi) {
            int r = 32 * wm + 16 * mi + g;
            float ri0 = 1.0f / denS[r];
            float ri1 = 1.0f / denS[r + 8];
            #pragma unroll
            for (int ni = 0; ni < 5; ++ni) {
                int c = 40 * wn + 8 * ni + 2 * tq;
                if (c < 64) {
                    float2 o0 = { accO[mi][ni][0] * ri0, accO[mi][ni][1] * ri0 };
                    float2 o1 = { accO[mi][ni][2] * ri1, accO[mi][ni][3] * ri1 };
                    *reinterpret_cast<float2*>(Op + (size_t)r * 64 + c)       = o0;
                    *reinterpret_cast<float2*>(Op + (size_t)(r + 8) * 64 + c) = o1;
                }
            }
        }
    }
}

// ---------------------------------------------------------------------------
// Launch
// ---------------------------------------------------------------------------
extern "C" void kernel_launch(void* const* d_in, const int* in_sizes, int n_in,
                              void* d_out, int out_size)
{
    const float* Q    = (const float*)d_in[0];
    const float* K    = (const float*)d_in[1];
    const float* V    = (const float*)d_in[2];
    const float* mask = (const float*)d_in[3];
    const float* proj = (const float*)d_in[4];
    float* out = (float*)d_out;

    cudaFuncSetAttribute(passA_tc, cudaFuncAttributeMaxDynamicSharedMemorySize, A_SMEM_BYTES);
    cudaFuncSetAttribute(passB_tc, cudaFuncAttributeMaxDynamicSharedMemorySize, B_SMEM_BYTES);

    zero_kernel<<<(BH * 64 * 256) / 256, 256>>>();
    passA_tc<<<BH * SPLIT, 256, A_SMEM_BYTES>>>(K, V, mask, proj);
    passB_tc<<<BH * SPLIT, 256, B_SMEM_BYTES>>>(Q, proj, out);
}

// round 12
// speedup vs baseline: 1.4765x; 1.4765x over previous
#include <cuda_runtime.h>
#include <cuda_bf16.h>

// Problem constants
#define BB 4
#define HH 8
#define NN 4096
#define DD 64
#define RR 256
#define BH (BB*HH)
#define SCALE 0.35355339059327373f   // 64^(-1/4)
#define EPS 0.001f

#define SPLIT 8                   // CTAs per (b,h)
#define ROWS_CTA (NN/SPLIT)       // 512
#define TILES (ROWS_CTA/128)      // 4

// ctxT scratch: [BH][80][256]  (rows 0..63 = ctx^T (d,feat), row 64 = ksum, 65..79 = 0)
__device__ float g_ctxT[BH * 80 * 256];

// ---------------------------------------------------------------------------
// helpers
// ---------------------------------------------------------------------------
__device__ __forceinline__ unsigned f2tf(float f) {
    unsigned u;
    asm("cvt.rna.tf32.f32 %0, %1;" : "=r"(u) : "f"(f));
    return u;
}

// D += A@B : m16n8k8 tf32, A row-major (4 regs), B col-major (2 regs), D f32 (4 regs)
__device__ __forceinline__ void mma8(float* d, const unsigned* a, const unsigned* b) {
    asm("mma.sync.aligned.m16n8k8.row.col.f32.tf32.tf32.f32 "
        "{%0,%1,%2,%3},{%4,%5,%6,%7},{%8,%9},{%0,%1,%2,%3};"
        : "+f"(d[0]), "+f"(d[1]), "+f"(d[2]), "+f"(d[3])
        : "r"(a[0]), "r"(a[1]), "r"(a[2]), "r"(a[3]), "r"(b[0]), "r"(b[1]));
}

// ---------------------------------------------------------------------------
// zero scratch (graph replays)
// ---------------------------------------------------------------------------
__global__ void zero_kernel() {
    int i = blockIdx.x * blockDim.x + threadIdx.x;
    if (i < BH * 80 * 256) g_ctxT[i] = 0.0f;
}

// ---------------------------------------------------------------------------
// Pass A (tensor): per tile of 128 rows:
//   GEMM1: phi_k[128, fc*64..] = relu((K*m) @ (proj*scale)^T) + eps   (chunks of 64 feats)
//   GEMM2 (flipped): ctx[feat64, d80] += phit[64,128] @ vt^T
//     (vt cols 0-63 = V*m, col 64 = 1 -> ksum, 65-79 = 0)
// smem words: projs 256*68=17408 | km 128*68=8704 | vt 80*132=10560 | phit x2 = 16896
// total 53568 words = 214272 B
// ---------------------------------------------------------------------------
#define A_SMEM_WORDS (17408 + 8704 + 10560 + 2*8448)
#define A_SMEM_BYTES (A_SMEM_WORDS * 4)

__global__ void __launch_bounds__(256) passA_tc(
    const float* __restrict__ Kg, const float* __restrict__ Vg,
    const float* __restrict__ maskg, const float* __restrict__ projg)
{
    extern __shared__ unsigned sm[];
    const int S_PROJ  = 0;
    const int S_KM    = 17408;
    const int S_VT    = 26112;
    const int S_PHIT0 = 36672;
    const int S_PHIT1 = 45120;

    const int t = threadIdx.x;
    const int warp = t >> 5, lane = t & 31;
    const int g = lane >> 2, tq = lane & 3;

    const int bh   = blockIdx.x / SPLIT;
    const int sl   = blockIdx.x % SPLIT;
    const int b    = bh / HH;
    const int row0 = sl * ROWS_CTA;

    // load projs = proj * SCALE (tf32), [feat][d] stride 68  (256*64 = 16384 elems)
    #pragma unroll 4
    for (int i = 0; i < 64; ++i) {
        int e = i * 256 + t;
        int f = e >> 6, d = e & 63;
        sm[S_PROJ + f * 68 + d] = f2tf(projg[e] * SCALE);
    }
    // vt rows 64..79: zero, then row 64 = ones
    for (int i = t; i < 16 * 132; i += 256) sm[S_VT + 64 * 132 + i] = 0u;
    if (t < 128) sm[S_VT + 64 * 132 + t] = __float_as_uint(1.0f);

    // persistent ctx accumulators (flipped): [chunk fc][ni (5x n8 over d)][4]
    float ctxA[4][5][4];
    #pragma unroll
    for (int a = 0; a < 4; ++a)
        #pragma unroll
        for (int n = 0; n < 5; ++n)
            #pragma unroll
            for (int j = 0; j < 4; ++j) ctxA[a][n][j] = 0.0f;

    const int wm = warp >> 1, wn = warp & 1;

    for (int tile = 0; tile < TILES; ++tile) {
        __syncthreads();   // guard km/vt overwrite vs previous tile's GEMM reads

        const float* Kp = Kg + ((size_t)bh * NN + row0 + tile * 128) * 64;
        const float* Vp = Vg + ((size_t)bh * NN + row0 + tile * 128) * 64;
        const float* mp = maskg + (size_t)b * NN + row0 + tile * 128;

        // km[row][d] = K*m (stride 68); vt[d][row] = V*m transposed (stride 132)
        #pragma unroll 4
        for (int i = 0; i < 32; ++i) {
            int e = i * 256 + t;
            int r = e >> 6, d = e & 63;
            float m = mp[r];
            sm[S_KM + r * 68 + d]  = f2tf(Kp[e] * m);
            sm[S_VT + d * 132 + r] = f2tf(Vp[e] * m);
        }
        __syncthreads();

        #pragma unroll
        for (int fc = 0; fc < 4; ++fc) {
            const int S_PHIT = (fc & 1) ? S_PHIT1 : S_PHIT0;

            // ---- GEMM1: phi chunk [128 x 64], warps 4m x 2n, warp tile 32x32 ----
            float acc[2][4][4];
            #pragma unroll
            for (int mi = 0; mi < 2; ++mi)
                #pragma unroll
                for (int ni = 0; ni < 4; ++ni)
                    #pragma unroll
                    for (int j = 0; j < 4; ++j) acc[mi][ni][j] = 0.0f;

            #pragma unroll
            for (int ks = 0; ks < 8; ++ks) {
                int kc = ks * 8 + tq;
                unsigned afr[2][4];
                #pragma unroll
                for (int mi = 0; mi < 2; ++mi) {
                    int r = 32 * wm + 16 * mi + g;
                    const unsigned* p = sm + S_KM + r * 68 + kc;
                    afr[mi][0] = p[0]; afr[mi][1] = p[8 * 68];
                    afr[mi][2] = p[4]; afr[mi][3] = p[8 * 68 + 4];
                }
                #pragma unroll
                for (int ni = 0; ni < 4; ++ni) {
                    int nf = fc * 64 + 32 * wn + 8 * ni + g;
                    const unsigned* p = sm + S_PROJ + nf * 68 + kc;
                    unsigned bfr[2] = { p[0], p[4] };
                    mma8(acc[0][ni], afr[0], bfr);
                    mma8(acc[1][ni], afr[1], bfr);
                }
            }

            // epilogue: relu + eps + cvt, store transposed phit[c][r] (stride 132)
            #pragma unroll
            for (int mi = 0; mi < 2; ++mi)
                #pragma unroll
                for (int ni = 0; ni < 4; ++ni) {
                    int r = 32 * wm + 16 * mi + g;
                    int c = 32 * wn + 8 * ni + 2 * tq;
                    sm[S_PHIT + c       * 132 + r    ] = f2tf(fmaxf(acc[mi][ni][0], 0.f) + EPS);
                    sm[S_PHIT + (c + 1) * 132 + r    ] = f2tf(fmaxf(acc[mi][ni][1], 0.f) + EPS);
                    sm[S_PHIT + c       * 132 + r + 8] = f2tf(fmaxf(acc[mi][ni][2], 0.f) + EPS);
                    sm[S_PHIT + (c + 1) * 132 + r + 8] = f2tf(fmaxf(acc[mi][ni][3], 0.f) + EPS);
                }
            __syncthreads();

            // ---- GEMM2 (flipped): ctx[feat,d] += phit[64,128] @ vt^T ----
            // warps 4m x 2n: m = 16 feats (1 frag), n = 40 d (5 frags)
            #pragma unroll
            for (int ks = 0; ks < 16; ++ks) {
                int kc = ks * 8 + tq;
                const unsigned* pa = sm + S_PHIT + (16 * wm + g) * 132 + kc;
                unsigned afr[4] = { pa[0], pa[8 * 132], pa[4], pa[8 * 132 + 4] };
                #pragma unroll
                for (int ni = 0; ni < 5; ++ni) {
                    const unsigned* pb = sm + S_VT + (40 * wn + 8 * ni + g) * 132 + kc;
                    unsigned bfr[2] = { pb[0], pb[4] };
                    mma8(ctxA[fc][ni], afr, bfr);
                }
            }
            // no trailing sync: next GEMM1 epilogue writes the other phit buffer;
            // buffer reuse (fc+2) is fenced by the sync after epilogue(fc+1).
        }
    }

    // write ctxT partials: C[m=feat][n=d] -> g_ctxT[d][feat]
    #pragma unroll
    for (int fc = 0; fc < 4; ++fc)
        #pragma unroll
        for (int ni = 0; ni < 5; ++ni) {
            int feat = fc * 64 + 16 * wm + g;
            int d    = 40 * wn + 8 * ni + 2 * tq;
            float* p0 = g_ctxT + ((size_t)bh * 80 + d    ) * 256 + feat;
            float* p1 = g_ctxT + ((size_t)bh * 80 + d + 1) * 256 + feat;
            atomicAdd(p0,     ctxA[fc][ni][0]);   // (feat,   d)
            atomicAdd(p1,     ctxA[fc][ni][1]);   // (feat,   d+1)
            atomicAdd(p0 + 8, ctxA[fc][ni][2]);   // (feat+8, d)
            atomicAdd(p1 + 8, ctxA[fc][ni][3]);   // (feat+8, d+1)
        }
}

// ---------------------------------------------------------------------------
// Pass B (tensor): per tile of 128 rows:
//   GEMM1': phi_q chunk = relu(Q @ projs^T) + eps   -> phiq[row][c] (stride 68)
//   GEMM3 : outraw[128,80] += phi_q @ ctxT^T        (col 64 = denominator)
// smem words: projs 17408 | qs 8704 | phiq 8704 | ctx 80*260=20800 | den 128
// ---------------------------------------------------------------------------
#define B_SMEM_WORDS (17408 + 8704 + 8704 + 20800 + 128)
#define B_SMEM_BYTES (B_SMEM_WORDS * 4)

__global__ void __launch_bounds__(256) passB_tc(
    const float* __restrict__ Qg, const float* __restrict__ projg,
    float* __restrict__ outg)
{
    extern __shared__ unsigned sm[];
    const int S_PROJ = 0;
    const int S_Q    = 17408;
    const int S_PHIQ = 26112;
    const int S_CTX  = 34816;
    const int S_DEN  = 55616;
    float* denS = (float*)(sm + S_DEN);

    const int t = threadIdx.x;
    const int warp = t >> 5, lane = t & 31;
    const int g = lane >> 2, tq = lane & 3;

    const int bh   = blockIdx.x / SPLIT;
    const int sl   = blockIdx.x % SPLIT;
    const int row0 = sl * ROWS_CTA;

    // projs (256*64 = 16384 elems)
    #pragma unroll 4
    for (int i = 0; i < 64; ++i) {
        int e = i * 256 + t;
        int f = e >> 6, d = e & 63;
        sm[S_PROJ + f * 68 + d] = f2tf(projg[e] * SCALE);
    }
    // ctxT [d][feat] stride 260
    #pragma unroll 4
    for (int i = 0; i < 80; ++i) {
        int e = i * 256 + t;
        int d = e >> 8, f = e & 255;
        sm[S_CTX + d * 260 + f] = f2tf(g_ctxT[(size_t)bh * 20480 + e]);
    }

    const int wm = warp >> 1, wn = warp & 1;

    for (int tile = 0; tile < TILES; ++tile) {
        __syncthreads();

        const float* Qp = Qg + ((size_t)bh * NN + row0 + tile * 128) * 64;
        #pragma unroll 4
        for (int i = 0; i < 32; ++i) {
            int e = i * 256 + t;
            int r = e >> 6, d = e & 63;
            sm[S_Q + r * 68 + d] = f2tf(Qp[e]);
        }
        __syncthreads();

        // persistent out accumulators: warp tile 32(m) x 40(n): 2 x 5 frags
        float accO[2][5][4];
        #pragma unroll
        for (int mi = 0; mi < 2; ++mi)
            #pragma unroll
            for (int ni = 0; ni < 5; ++ni)
                #pragma unroll
                for (int j = 0; j < 4; ++j) accO[mi][ni][j] = 0.0f;

        #pragma unroll
        for (int fc = 0; fc < 4; ++fc) {
            // ---- GEMM1': phi_q chunk [128 x 64] ----
            float acc[2][4][4];
            #pragma unroll
            for (int mi = 0; mi < 2; ++mi)
                #pragma unroll
                for (int ni = 0; ni < 4; ++ni)
                    #pragma unroll
                    for (int j = 0; j < 4; ++j) acc[mi][ni][j] = 0.0f;

            #pragma unroll
            for (int ks = 0; ks < 8; ++ks) {
                int kc = ks * 8 + tq;
                unsigned afr[2][4];
                #pragma unroll
                for (int mi = 0; mi < 2; ++mi) {
                    int r = 32 * wm + 16 * mi + g;
                    const unsigned* p = sm + S_Q + r * 68 + kc;
                    afr[mi][0] = p[0]; afr[mi][1] = p[8 * 68];
                    afr[mi][2] = p[4]; afr[mi][3] = p[8 * 68 + 4];
                }
                #pragma unroll
                for (int ni = 0; ni < 4; ++ni) {
                    int nf = fc * 64 + 32 * wn + 8 * ni + g;
                    const unsigned* p = sm + S_PROJ + nf * 68 + kc;
                    unsigned bfr[2] = { p[0], p[4] };
                    mma8(acc[0][ni], afr[0], bfr);
                    mma8(acc[1][ni], afr[1], bfr);
                }
            }
            // store phiq[row][c] (chunk-local, stride 68)
            #pragma unroll
            for (int mi = 0; mi < 2; ++mi)
                #pragma unroll
                for (int ni = 0; ni < 4; ++ni) {
                    int r = 32 * wm + 16 * mi + g;
                    int c = 32 * wn + 8 * ni + 2 * tq;
                    sm[S_PHIQ + r       * 68 + c    ] = f2tf(fmaxf(acc[mi][ni][0], 0.f) + EPS);
                    sm[S_PHIQ + r       * 68 + c + 1] = f2tf(fmaxf(acc[mi][ni][1], 0.f) + EPS);
                    sm[S_PHIQ + (r + 8) * 68 + c    ] = f2tf(fmaxf(acc[mi][ni][2], 0.f) + EPS);
                    sm[S_PHIQ + (r + 8) * 68 + c + 1] = f2tf(fmaxf(acc[mi][ni][3], 0.f) + EPS);
                }
            __syncthreads();

            // ---- GEMM3 partial: outraw += phiq @ ctxT^T  (k = 64 chunk feats) ----
            #pragma unroll
            for (int ks = 0; ks < 8; ++ks) {
                int kc = ks * 8 + tq;
                unsigned afr[2][4];
                #pragma unroll
                for (int mi = 0; mi < 2; ++mi) {
                    int r = 32 * wm + 16 * mi + g;
                    const unsigned* p = sm + S_PHIQ + r * 68 + kc;
                    afr[mi][0] = p[0]; afr[mi][1] = p[8 * 68];
                    afr[mi][2] = p[4]; afr[mi][3] = p[8 * 68 + 4];
                }
                #pragma unroll
                for (int ni = 0; ni < 5; ++ni) {
                    int n = 40 * wn + 8 * ni + g;
                    const unsigned* p = sm + S_CTX + n * 260 + fc * 64 + kc;
                    unsigned bfr[2] = { p[0], p[4] };
                    mma8(accO[0][ni], afr[0], bfr);
                    mma8(accO[1][ni], afr[1], bfr);
                }
            }
            __syncthreads();   // phiq reuse guard
        }

        // denominator: col 64 lives in warps wn==1, frag ni=3, lanes tq==0, elem 0/2
        if (wn == 1 && tq == 0) {
            #pragma unroll
            for (int mi = 0; mi < 2; ++mi) {
                int r = 32 * wm + 16 * mi + g;
                denS[r]     = accO[mi][3][0];
                denS[r + 8] = accO[mi][3][2];
            }
        }
        __syncthreads();

        // scaled store
        float* Op = outg + ((size_t)bh * NN + row0 + tile * 128) * 64;
        #pragma unroll
        for (int mi = 0; mi < 2; ++mi) {
            int r = 32 * wm + 16 * mi + g;
            float ri0 = 1.0f / denS[r];
            float ri1 = 1.0f / denS[r + 8];
            #pragma unroll
            for (int ni = 0; ni < 5; ++ni) {
                int c = 40 * wn + 8 * ni + 2 * tq;
                if (c < 64) {
                    float2 o0 = { accO[mi][ni][0] * ri0, accO[mi][ni][1] * ri0 };
                    float2 o1 = { accO[mi][ni][2] * ri1, accO[mi][ni][3] * ri1 };
                    *reinterpret_cast<float2*>(Op + (size_t)r * 64 + c)       = o0;
                    *reinterpret_cast<float2*>(Op + (size_t)(r + 8) * 64 + c) = o1;
                }
            }
        }
    }
}

// ---------------------------------------------------------------------------
// Launch
// ---------------------------------------------------------------------------
extern "C" void kernel_launch(void* const* d_in, const int* in_sizes, int n_in,
                              void* d_out, int out_size)
{
    const float* Q    = (const float*)d_in[0];
    const float* K    = (const float*)d_in[1];
    const float* V    = (const float*)d_in[2];
    const float* mask = (const float*)d_in[3];
    const float* proj = (const float*)d_in[4];
    float* out = (float*)d_out;

    cudaFuncSetAttribute(passA_tc, cudaFuncAttributeMaxDynamicSharedMemorySize, A_SMEM_BYTES);
    cudaFuncSetAttribute(passB_tc, cudaFuncAttributeMaxDynamicSharedMemorySize, B_SMEM_BYTES);

    zero_kernel<<<(BH * 80 * 256) / 256, 256>>>();
    passA_tc<<<BH * SPLIT, 256, A_SMEM_BYTES>>>(K, V, mask, proj);
    passB_tc<<<BH * SPLIT, 256, B_SMEM_BYTES>>>(Q, proj, out);
}

// round 16
// speedup vs baseline: 1.8483x; 1.2518x over previous
#include <cuda_runtime.h>
#include <cuda_bf16.h>

// Problem constants
#define BB 4
#define HH 8
#define NN 4096
#define DD 64
#define RR 256
#define BH (BB*HH)
#define SCALE 0.35355339059327373f   // 64^(-1/4)
#define EPS 0.001f

#define SPLIT 4                   // CTAs per (b,h)  -> 128 CTAs, single wave
#define ROWS_CTA (NN/SPLIT)       // 1024
#define TILES (ROWS_CTA/128)      // 8

// ctxT scratch: [BH][80][256]  (rows 0..63 = ctx^T (d,feat), row 64 = ksum, 65..79 = 0)
__device__ float g_ctxT[BH * 80 * 256];

// ---------------------------------------------------------------------------
// helpers
// ---------------------------------------------------------------------------
__device__ __forceinline__ unsigned f2tf(float f) {
    unsigned u;
    asm("cvt.rna.tf32.f32 %0, %1;" : "=r"(u) : "f"(f));
    return u;
}

// D += A@B : m16n8k8 tf32, A row-major (4 regs), B col-major (2 regs), D f32 (4 regs)
__device__ __forceinline__ void mma8(float* d, const unsigned* a, const unsigned* b) {
    asm("mma.sync.aligned.m16n8k8.row.col.f32.tf32.tf32.f32 "
        "{%0,%1,%2,%3},{%4,%5,%6,%7},{%8,%9},{%0,%1,%2,%3};"
        : "+f"(d[0]), "+f"(d[1]), "+f"(d[2]), "+f"(d[3])
        : "r"(a[0]), "r"(a[1]), "r"(a[2]), "r"(a[3]), "r"(b[0]), "r"(b[1]));
}

// ---------------------------------------------------------------------------
// zero scratch (graph replays)
// ---------------------------------------------------------------------------
__global__ void zero_kernel() {
    int i = blockIdx.x * blockDim.x + threadIdx.x;
    if (i < BH * 80 * 256) g_ctxT[i] = 0.0f;
}

// ---------------------------------------------------------------------------
// Pass A (tensor): per tile of 128 rows:
//   GEMM1: phi_k[128, fc*64..] = relu((K*m) @ (proj*scale)^T) + eps   (chunks of 64 feats)
//   GEMM2 (flipped): ctx[feat64, d80] += phit[64,128] @ vt^T
//     (vt cols 0-63 = V*m, col 64 = 1 -> ksum, 65-79 = 0)
// smem words: projs 17408 | km 8704 | vt 10560 | phit x2 16896  = 53568 (214272 B, fits)
// ---------------------------------------------------------------------------
#define A_SMEM_WORDS (17408 + 8704 + 10560 + 2*8448)
#define A_SMEM_BYTES (A_SMEM_WORDS * 4)

__global__ void __launch_bounds__(256) passA_tc(
    const float* __restrict__ Kg, const float* __restrict__ Vg,
    const float* __restrict__ maskg, const float* __restrict__ projg)
{
    extern __shared__ unsigned sm[];
    const int S_PROJ  = 0;
    const int S_KM    = 17408;
    const int S_VT    = 26112;
    const int S_PHIT0 = 36672;
    const int S_PHIT1 = 45120;

    const int t = threadIdx.x;
    const int warp = t >> 5, lane = t & 31;
    const int g = lane >> 2, tq = lane & 3;

    const int bh   = blockIdx.x / SPLIT;
    const int sl   = blockIdx.x % SPLIT;
    const int b    = bh / HH;
    const int row0 = sl * ROWS_CTA;

    // projs = proj * SCALE (tf32), [feat][d] stride 68  (16384 elems, float4 loads)
    #pragma unroll 4
    for (int i = 0; i < 16; ++i) {
        int e4 = i * 256 + t;                  // float4 index
        int f = e4 >> 4, d = (e4 & 15) * 4;
        float4 p = reinterpret_cast<const float4*>(projg)[e4];
        uint4 u = { f2tf(p.x * SCALE), f2tf(p.y * SCALE),
                    f2tf(p.z * SCALE), f2tf(p.w * SCALE) };
        *reinterpret_cast<uint4*>(sm + S_PROJ + f * 68 + d) = u;
    }
    // vt rows 64..79: zero, then row 64 = ones
    for (int i = t; i < 16 * 132; i += 256) sm[S_VT + 64 * 132 + i] = 0u;
    if (t < 128) sm[S_VT + 64 * 132 + t] = __float_as_uint(1.0f);

    // persistent ctx accumulators (flipped): [chunk fc][ni (5x n8 over d)][4]
    float ctxA[4][5][4];
    #pragma unroll
    for (int a = 0; a < 4; ++a)
        #pragma unroll
        for (int n = 0; n < 5; ++n)
            #pragma unroll
            for (int j = 0; j < 4; ++j) ctxA[a][n][j] = 0.0f;

    const int wm = warp >> 1, wn = warp & 1;

    for (int tile = 0; tile < TILES; ++tile) {
        __syncthreads();   // guard km/vt overwrite vs previous tile's GEMM reads

        const float* Kp = Kg + ((size_t)bh * NN + row0 + tile * 128) * 64;
        const float* Vp = Vg + ((size_t)bh * NN + row0 + tile * 128) * 64;
        const float* mp = maskg + (size_t)b * NN + row0 + tile * 128;

        // km[row][d] = K*m (stride 68, uint4 stores); vt[d][row] = V*m transposed
        #pragma unroll 2
        for (int i = 0; i < 8; ++i) {
            int e4 = i * 256 + t;                // float4 index within 128x64 tile
            int r = e4 >> 4, d = (e4 & 15) * 4;
            float m = mp[r];
            float4 kk = reinterpret_cast<const float4*>(Kp)[e4];
            float4 vv = reinterpret_cast<const float4*>(Vp)[e4];
            uint4 ku = { f2tf(kk.x * m), f2tf(kk.y * m), f2tf(kk.z * m), f2tf(kk.w * m) };
            *reinterpret_cast<uint4*>(sm + S_KM + r * 68 + d) = ku;
            sm[S_VT + (d + 0) * 132 + r] = f2tf(vv.x * m);
            sm[S_VT + (d + 1) * 132 + r] = f2tf(vv.y * m);
            sm[S_VT + (d + 2) * 132 + r] = f2tf(vv.z * m);
            sm[S_VT + (d + 3) * 132 + r] = f2tf(vv.w * m);
        }
        __syncthreads();

        #pragma unroll
        for (int fc = 0; fc < 4; ++fc) {
            const int S_PHIT = (fc & 1) ? S_PHIT1 : S_PHIT0;

            // ---- GEMM1: phi chunk [128 x 64], warps 4m x 2n, warp tile 32x32 ----
            float acc[2][4][4];
            #pragma unroll
            for (int mi = 0; mi < 2; ++mi)
                #pragma unroll
                for (int ni = 0; ni < 4; ++ni)
                    #pragma unroll
                    for (int j = 0; j < 4; ++j) acc[mi][ni][j] = 0.0f;

            #pragma unroll
            for (int ks = 0; ks < 8; ++ks) {
                int kc = ks * 8 + tq;
                unsigned afr[2][4];
                #pragma unroll
                for (int mi = 0; mi < 2; ++mi) {
                    int r = 32 * wm + 16 * mi + g;
                    const unsigned* p = sm + S_KM + r * 68 + kc;
                    afr[mi][0] = p[0]; afr[mi][1] = p[8 * 68];
                    afr[mi][2] = p[4]; afr[mi][3] = p[8 * 68 + 4];
                }
                #pragma unroll
                for (int ni = 0; ni < 4; ++ni) {
                    int nf = fc * 64 + 32 * wn + 8 * ni + g;
                    const unsigned* p = sm + S_PROJ + nf * 68 + kc;
                    unsigned bfr[2] = { p[0], p[4] };
                    mma8(acc[0][ni], afr[0], bfr);
                    mma8(acc[1][ni], afr[1], bfr);
                }
            }

            // epilogue: relu + eps + cvt, store transposed phit[c][r] (stride 132)
            #pragma unroll
            for (int mi = 0; mi < 2; ++mi)
                #pragma unroll
                for (int ni = 0; ni < 4; ++ni) {
                    int r = 32 * wm + 16 * mi + g;
                    int c = 32 * wn + 8 * ni + 2 * tq;
                    sm[S_PHIT + c       * 132 + r    ] = f2tf(fmaxf(acc[mi][ni][0], 0.f) + EPS);
                    sm[S_PHIT + (c + 1) * 132 + r    ] = f2tf(fmaxf(acc[mi][ni][1], 0.f) + EPS);
                    sm[S_PHIT + c       * 132 + r + 8] = f2tf(fmaxf(acc[mi][ni][2], 0.f) + EPS);
                    sm[S_PHIT + (c + 1) * 132 + r + 8] = f2tf(fmaxf(acc[mi][ni][3], 0.f) + EPS);
                }
            __syncthreads();

            // ---- GEMM2 (flipped): ctx[feat,d] += phit[64,128] @ vt^T ----
            // warps 4m x 2n: m = 16 feats (1 frag), n = 40 d (5 frags)
            #pragma unroll
            for (int ks = 0; ks < 16; ++ks) {
                int kc = ks * 8 + tq;
                const unsigned* pa = sm + S_PHIT + (16 * wm + g) * 132 + kc;
                unsigned afr[4] = { pa[0], pa[8 * 132], pa[4], pa[8 * 132 + 4] };
                #pragma unroll
                for (int ni = 0; ni < 5; ++ni) {
                    const unsigned* pb = sm + S_VT + (40 * wn + 8 * ni + g) * 132 + kc;
                    unsigned bfr[2] = { pb[0], pb[4] };
                    mma8(ctxA[fc][ni], afr, bfr);
                }
            }
            // no trailing sync: next GEMM1 epilogue writes the other phit buffer;
            // buffer reuse (fc+2) is fenced by the sync after epilogue(fc+1).
        }
    }

    // write ctxT partials: C[m=feat][n=d] -> g_ctxT[d][feat]
    #pragma unroll
    for (int fc = 0; fc < 4; ++fc)
        #pragma unroll
        for (int ni = 0; ni < 5; ++ni) {
            int feat = fc * 64 + 16 * wm + g;
            int d    = 40 * wn + 8 * ni + 2 * tq;
            float* p0 = g_ctxT + ((size_t)bh * 80 + d    ) * 256 + feat;
            float* p1 = g_ctxT + ((size_t)bh * 80 + d + 1) * 256 + feat;
            atomicAdd(p0,     ctxA[fc][ni][0]);   // (feat,   d)
            atomicAdd(p1,     ctxA[fc][ni][1]);   // (feat,   d+1)
            atomicAdd(p0 + 8, ctxA[fc][ni][2]);   // (feat+8, d)
            atomicAdd(p1 + 8, ctxA[fc][ni][3]);   // (feat+8, d+1)
        }
}

// ---------------------------------------------------------------------------
// Pass B (tensor): per tile of 128 rows:
//   GEMM1': phi_q chunk = relu(Q @ projs^T) + eps   -> phiq[row][c] (stride 68)
//   GEMM3 : outraw[128,80] += phi_q @ ctxT^T        (col 64 = denominator)
// smem words: projs 17408 | qs 8704 | phiq 8704 | ctx 20800 | den 128
// total 55744 words = 222976 B  (< 227 KB limit; verified launchable at this size)
// ---------------------------------------------------------------------------
#define B_SMEM_WORDS (17408 + 8704 + 8704 + 20800 + 128)
#define B_SMEM_BYTES (B_SMEM_WORDS * 4)

__global__ void __launch_bounds__(256) passB_tc(
    const float* __restrict__ Qg, const float* __restrict__ projg,
    float* __restrict__ outg)
{
    extern __shared__ unsigned sm[];
    const int S_PROJ = 0;
    const int S_Q    = 17408;
    const int S_PHIQ = 26112;
    const int S_CTX  = 34816;
    const int S_DEN  = 55616;
    float* denS = (float*)(sm + S_DEN);

    const int t = threadIdx.x;
    const int warp = t >> 5, lane = t & 31;
    const int g = lane >> 2, tq = lane & 3;

    const int bh   = blockIdx.x / SPLIT;
    const int sl   = blockIdx.x % SPLIT;
    const int row0 = sl * ROWS_CTA;

    // projs (16384 elems, float4 loads)
    #pragma unroll 4
    for (int i = 0; i < 16; ++i) {
        int e4 = i * 256 + t;
        int f = e4 >> 4, d = (e4 & 15) * 4;
        float4 p = reinterpret_cast<const float4*>(projg)[e4];
        uint4 u = { f2tf(p.x * SCALE), f2tf(p.y * SCALE),
                    f2tf(p.z * SCALE), f2tf(p.w * SCALE) };
        *reinterpret_cast<uint4*>(sm + S_PROJ + f * 68 + d) = u;
    }
    // ctxT [d][feat] stride 260
    #pragma unroll 4
    for (int i = 0; i < 80; ++i) {
        int e = i * 256 + t;
        int d = e >> 8, f = e & 255;
        sm[S_CTX + d * 260 + f] = f2tf(g_ctxT[(size_t)bh * 20480 + e]);
    }

    const int wm = warp >> 1, wn = warp & 1;

    for (int tile = 0; tile < TILES; ++tile) {
        __syncthreads();

        const float* Qp = Qg + ((size_t)bh * NN + row0 + tile * 128) * 64;
        #pragma unroll 2
        for (int i = 0; i < 8; ++i) {
            int e4 = i * 256 + t;
            int r = e4 >> 4, d = (e4 & 15) * 4;
            float4 q = reinterpret_cast<const float4*>(Qp)[e4];
            uint4 u = { f2tf(q.x), f2tf(q.y), f2tf(q.z), f2tf(q.w) };
            *reinterpret_cast<uint4*>(sm + S_Q + r * 68 + d) = u;
        }
        __syncthreads();

        // persistent out accumulators: warp tile 32(m) x 40(n): 2 x 5 frags
        float accO[2][5][4];
        #pragma unroll
        for (int mi = 0; mi < 2; ++mi)
            #pragma unroll
            for (int ni = 0; ni < 5; ++ni)
                #pragma unroll
                for (int j = 0; j < 4; ++j) accO[mi][ni][j] = 0.0f;

        #pragma unroll
        for (int fc = 0; fc < 4; ++fc) {
            // ---- GEMM1': phi_q chunk [128 x 64] ----
            float acc[2][4][4];
            #pragma unroll
            for (int mi = 0; mi < 2; ++mi)
                #pragma unroll
                for (int ni = 0; ni < 4; ++ni)
                    #pragma unroll
                    for (int j = 0; j < 4; ++j) acc[mi][ni][j] = 0.0f;

            #pragma unroll
            for (int ks = 0; ks < 8; ++ks) {
                int kc = ks * 8 + tq;
                unsigned afr[2][4];
                #pragma unroll
                for (int mi = 0; mi < 2; ++mi) {
                    int r = 32 * wm + 16 * mi + g;
                    const unsigned* p = sm + S_Q + r * 68 + kc;
                    afr[mi][0] = p[0]; afr[mi][1] = p[8 * 68];
                    afr[mi][2] = p[4]; afr[mi][3] = p[8 * 68 + 4];
                }
                #pragma unroll
                for (int ni = 0; ni < 4; ++ni) {
                    int nf = fc * 64 + 32 * wn + 8 * ni + g;
                    const unsigned* p = sm + S_PROJ + nf * 68 + kc;
                    unsigned bfr[2] = { p[0], p[4] };
                    mma8(acc[0][ni], afr[0], bfr);
                    mma8(acc[1][ni], afr[1], bfr);
                }
            }
            // store phiq[row][c] (chunk-local, stride 68)
            #pragma unroll
            for (int mi = 0; mi < 2; ++mi)
                #pragma unroll
                for (int ni = 0; ni < 4; ++ni) {
                    int r = 32 * wm + 16 * mi + g;
                    int c = 32 * wn + 8 * ni + 2 * tq;
                    sm[S_PHIQ + r       * 68 + c    ] = f2tf(fmaxf(acc[mi][ni][0], 0.f) + EPS);
                    sm[S_PHIQ + r       * 68 + c + 1] = f2tf(fmaxf(acc[mi][ni][1], 0.f) + EPS);
                    sm[S_PHIQ + (r + 8) * 68 + c    ] = f2tf(fmaxf(acc[mi][ni][2], 0.f) + EPS);
                    sm[S_PHIQ + (r + 8) * 68 + c + 1] = f2tf(fmaxf(acc[mi][ni][3], 0.f) + EPS);
                }
            __syncthreads();

            // ---- GEMM3 partial: outraw += phiq @ ctxT^T  (k = 64 chunk feats) ----
            #pragma unroll
            for (int ks = 0; ks < 8; ++ks) {
                int kc = ks * 8 + tq;
                unsigned afr[2][4];
                #pragma unroll
                for (int mi = 0; mi < 2; ++mi) {
                    int r = 32 * wm + 16 * mi + g;
                    const unsigned* p = sm + S_PHIQ + r * 68 + kc;
                    afr[mi][0] = p[0]; afr[mi][1] = p[8 * 68];
                    afr[mi][2] = p[4]; afr[mi][3] = p[8 * 68 + 4];
                }
                #pragma unroll
                for (int ni = 0; ni < 5; ++ni) {
                    int n = 40 * wn + 8 * ni + g;
                    const unsigned* p = sm + S_CTX + n * 260 + fc * 64 + kc;
                    unsigned bfr[2] = { p[0], p[4] };
                    mma8(accO[0][ni], afr[0], bfr);
                    mma8(accO[1][ni], afr[1], bfr);
                }
            }
            __syncthreads();   // phiq reuse guard
        }

        // denominator: col 64 lives in warps wn==1, frag ni=3, lanes tq==0, elem 0/2
        if (wn == 1 && tq == 0) {
            #pragma unroll
            for (int mi = 0; mi < 2; ++mi) {
                int r = 32 * wm + 16 * mi + g;
                denS[r]     = accO[mi][3][0];
                denS[r + 8] = accO[mi][3][2];
            }
        }
        __syncthreads();

        // scaled store
        float* Op = outg + ((size_t)bh * NN + row0 + tile * 128) * 64;
        #pragma unroll
        for (int mi = 0; mi < 2; ++mi) {
            int r = 32 * wm + 16 * mi + g;
            float ri0 = 1.0f / denS[r];
            float ri1 = 1.0f / denS[r + 8];
            #pragma unroll
            for (int ni = 0; ni < 5; ++ni) {
                int c = 40 * wn + 8 * ni + 2 * tq;
                if (c < 64) {
                    float2 o0 = { accO[mi][ni][0] * ri0, accO[mi][ni][1] * ri0 };
                    float2 o1 = { accO[mi][ni][2] * ri1, accO[mi][ni][3] * ri1 };
                    *reinterpret_cast<float2*>(Op + (size_t)r * 64 + c)       = o0;
                    *reinterpret_cast<float2*>(Op + (size_t)(r + 8) * 64 + c) = o1;
                }
            }
        }
    }
}

// ---------------------------------------------------------------------------
// Launch
// ---------------------------------------------------------------------------
extern "C" void kernel_launch(void* const* d_in, const int* in_sizes, int n_in,
                              void* d_out, int out_size)
{
    const float* Q    = (const float*)d_in[0];
    const float* K    = (const float*)d_in[1];
    const float* V    = (const float*)d_in[2];
    const float* mask = (const float*)d_in[3];
    const float* proj = (const float*)d_in[4];
    float* out = (float*)d_out;

    cudaFuncSetAttribute(passA_tc, cudaFuncAttributeMaxDynamicSharedMemorySize, A_SMEM_BYTES);
    cudaFuncSetAttribute(passB_tc, cudaFuncAttributeMaxDynamicSharedMemorySize, B_SMEM_BYTES);

    zero_kernel<<<(BH * 80 * 256) / 256, 256>>>();
    passA_tc<<<BH * SPLIT, 256, A_SMEM_BYTES>>>(K, V, mask, proj);
    passB_tc<<<BH * SPLIT, 256, B_SMEM_BYTES>>>(Q, proj, out);
}